// round 1
// baseline (speedup 1.0000x reference)
#include <cuda_runtime.h>
#include <cstdint>

#define BB 32
#define AA 1024
#define DD 128
#define THR2 0.0025f
#define TM 32   // MLP rows per block

// Scratch (allocation-free rule: __device__ globals)
__device__ float g_sums[BB * AA * DD];   // per-(batch,group) embedding sums
__device__ int   g_cnt[BB * AA];         // per-(batch,group) member counts

__device__ __forceinline__ float gelu_exact(float x) {
    return 0.5f * x * (1.0f + erff(x * 0.70710678118654752f));
}

// ---------------------------------------------------------------------------
// Kernel 1: per-batch greedy proximity clustering + segment-sum pooling.
// One block of 1024 threads per batch.
// SMEM: adj bitmatrix [A][32] u32 (128KB) + coords (8KB) + assigned (4KB)
//       + cnt (4KB) + valid words (128B)  = 147,584 B dynamic.
// ---------------------------------------------------------------------------
__global__ __launch_bounds__(1024, 1)
void cluster_pool_kernel(const float* __restrict__ emb,
                         const float* __restrict__ coords,
                         const int*   __restrict__ mask,
                         float* __restrict__ out_mask,   // may be null
                         float* __restrict__ out_a2g)    // may be null
{
    extern __shared__ unsigned char smem_raw[];
    uint32_t* adj     = (uint32_t*)smem_raw;                       // AA*32 u32
    float2*   sc      = (float2*)(smem_raw + (size_t)AA * 32 * 4); // AA
    int*      s_asg   = (int*)((unsigned char*)sc + AA * 8);       // AA
    int*      s_cnt   = (int*)(s_asg + AA);                        // AA
    uint32_t* s_valid = (uint32_t*)(s_cnt + AA);                   // 32

    const int b   = blockIdx.x;
    const int tid = threadIdx.x;          // 0..1023
    const int w   = tid >> 5;
    const int l   = tid & 31;

    // load coords, init assigned, validity ballot
    {
        const float2* gc = (const float2*)(coords + (size_t)b * AA * 2);
        sc[tid] = gc[tid];
        s_asg[tid] = -1;
        int v = (mask[(size_t)b * AA + tid] != 0);
        unsigned m = __ballot_sync(0xffffffffu, v);
        if (l == 0) s_valid[w] = m;
    }
    __syncthreads();

    // proximity bit-matrix: adj[row*32 + word], bit j of word = (dist^2 < thr^2)
    for (int task = w; task < AA * 32; task += 32) {
        const int row  = task >> 5;
        const int word = task & 31;
        float2 ci = sc[row];
        float2 cj = sc[(word << 5) + l];
        float dx = ci.x - cj.x;
        float dy = ci.y - cj.y;
        // match plain (non-fused) evaluation of dx*dx + dy*dy
        float d2 = __fadd_rn(__fmul_rn(dx, dx), __fmul_rn(dy, dy));
        unsigned m = __ballot_sync(0xffffffffu, d2 < THR2);
        if (l == 0) adj[task] = m;
    }
    __syncthreads();

    // greedy scan on warp 0; U = unassigned-valid bitmask, one u32 per lane
    if (w == 0) {
        unsigned U = s_valid[l];
        int gid = 0;
        for (int i = 0; i < AA; i++) {
            unsigned Uw = __shfl_sync(0xffffffffu, U, i >> 5);
            if ((Uw >> (i & 31)) & 1u) {
                unsigned take = adj[i * 32 + l] & U;   // includes i itself
                U &= ~take;
                unsigned t = take;
                while (t) {
                    int bit = __ffs(t) - 1;
                    t &= t - 1u;
                    s_asg[(l << 5) + bit] = gid;
                }
                int c = __reduce_add_sync(0xffffffffu, (int)__popc(take));
                if (l == 0) s_cnt[gid] = c;
                gid++;
            }
        }
        for (int g = gid + l; g < AA; g += 32) s_cnt[g] = 0;
    }
    __syncthreads();

    // emit counts, agent_to_group, group_mask; zero this batch's sums slice
    {
        int asg = s_asg[tid];
        int cnt = s_cnt[tid];
        g_cnt[(size_t)b * AA + tid] = cnt;
        if (out_a2g)  out_a2g[(size_t)b * AA + tid]  = (float)asg;
        if (out_mask) out_mask[(size_t)b * AA + tid] = (cnt > 0) ? 1.0f : 0.0f;
    }
    {
        float4* s4 = (float4*)(g_sums + (size_t)b * AA * DD);
        const float4 z = make_float4(0.f, 0.f, 0.f, 0.f);
        for (int i = tid; i < AA * DD / 4; i += 1024) s4[i] = z;
    }
    __syncthreads();

    // segment-sum pooling (block-private slice of g_sums; atomics within block)
    {
        float* sums = g_sums + (size_t)b * AA * DD;
        const float* eb = emb + (size_t)b * AA * DD;
        for (int i = tid; i < AA * DD; i += 1024) {
            int a = i >> 7;
            int d = i & 127;
            int g = s_asg[a];
            if (g >= 0) atomicAdd(&sums[g * DD + d], eb[i]);
        }
    }
}

// ---------------------------------------------------------------------------
// Kernel 2: tokens = sums / max(cnt,1); out = gelu(tokens@W1+b1)@W2 + b2
// 256 threads, TM=32 rows per block. Both weight matrices resident in SMEM.
// 8 warps x 4 rows, lane covers 4 consecutive output columns (float4 LDS).
// SMEM: W1 64KB + W2 64KB + x 16KB + h 16KB = 163,840 B dynamic.
// ---------------------------------------------------------------------------
__global__ __launch_bounds__(256, 1)
void mlp_kernel(const float* __restrict__ W1, const float* __restrict__ b1,
                const float* __restrict__ W2, const float* __restrict__ b2,
                float* __restrict__ out)
{
    extern __shared__ float sm[];
    float* sW1 = sm;            // 16384
    float* sW2 = sm + 16384;    // 16384
    float* sx  = sm + 32768;    // 4096
    float* sh  = sm + 36864;    // 4096

    const int tid = threadIdx.x;

    // stage weights
    {
        const float4* W14 = (const float4*)W1;
        const float4* W24 = (const float4*)W2;
        float4* sW14 = (float4*)sW1;
        float4* sW24 = (float4*)sW2;
        for (int i = tid; i < DD * DD / 4; i += 256) {
            sW14[i] = W14[i];
            sW24[i] = W24[i];
        }
    }
    // stage x = sums / max(cnt,1)
    {
        const int rbase = blockIdx.x * TM;
        for (int i = tid; i < TM * DD; i += 256) {
            int r  = i >> 7;
            int gr = rbase + r;
            int c  = g_cnt[gr];
            float inv = 1.0f / (float)(c > 1 ? c : 1);
            sx[i] = g_sums[(size_t)gr * DD + (i & 127)] * inv;
        }
    }
    __syncthreads();

    const int wp   = tid >> 5;
    const int lane = tid & 31;
    const int r0   = wp * 4;      // 4 rows per warp
    const int c0   = lane * 4;    // 4 cols per lane

    // ---- layer 1 ----
    float acc[4][4];
#pragma unroll
    for (int i = 0; i < 4; i++)
#pragma unroll
        for (int j = 0; j < 4; j++) acc[i][j] = 0.0f;

#pragma unroll 4
    for (int k = 0; k < DD; k++) {
        float4 wv = *(const float4*)&sW1[k * DD + c0];
#pragma unroll
        for (int i = 0; i < 4; i++) {
            float xv = sx[(r0 + i) * DD + k];
            acc[i][0] = fmaf(xv, wv.x, acc[i][0]);
            acc[i][1] = fmaf(xv, wv.y, acc[i][1]);
            acc[i][2] = fmaf(xv, wv.z, acc[i][2]);
            acc[i][3] = fmaf(xv, wv.w, acc[i][3]);
        }
    }
    {
        float4 bv = *(const float4*)&b1[c0];
#pragma unroll
        for (int i = 0; i < 4; i++) {
            float4 hv;
            hv.x = gelu_exact(acc[i][0] + bv.x);
            hv.y = gelu_exact(acc[i][1] + bv.y);
            hv.z = gelu_exact(acc[i][2] + bv.z);
            hv.w = gelu_exact(acc[i][3] + bv.w);
            *(float4*)&sh[(r0 + i) * DD + c0] = hv;
        }
    }
    __syncthreads();

    // ---- layer 2 ----
#pragma unroll
    for (int i = 0; i < 4; i++)
#pragma unroll
        for (int j = 0; j < 4; j++) acc[i][j] = 0.0f;

#pragma unroll 4
    for (int k = 0; k < DD; k++) {
        float4 wv = *(const float4*)&sW2[k * DD + c0];
#pragma unroll
        for (int i = 0; i < 4; i++) {
            float hv = sh[(r0 + i) * DD + k];
            acc[i][0] = fmaf(hv, wv.x, acc[i][0]);
            acc[i][1] = fmaf(hv, wv.y, acc[i][1]);
            acc[i][2] = fmaf(hv, wv.z, acc[i][2]);
            acc[i][3] = fmaf(hv, wv.w, acc[i][3]);
        }
    }
    {
        const int rbase = blockIdx.x * TM;
        float4 bv = *(const float4*)&b2[c0];
#pragma unroll
        for (int i = 0; i < 4; i++) {
            float4 ov;
            ov.x = acc[i][0] + bv.x;
            ov.y = acc[i][1] + bv.y;
            ov.z = acc[i][2] + bv.z;
            ov.w = acc[i][3] + bv.w;
            *(float4*)&out[(size_t)(rbase + r0 + i) * DD + c0] = ov;
        }
    }
}

// ---------------------------------------------------------------------------
extern "C" void kernel_launch(void* const* d_in, const int* in_sizes, int n_in,
                              void* d_out, int out_size)
{
    const float* emb    = (const float*)d_in[0];
    const float* coords = (const float*)d_in[1];
    const int*   mask   = (const int*)d_in[2];
    const float* W1     = (const float*)d_in[3];
    const float* b1     = (const float*)d_in[4];
    const float* W2     = (const float*)d_in[5];
    const float* b2     = (const float*)d_in[6];

    float* out = (float*)d_out;
    const int tok_elems = BB * AA * DD;
    float* out_mask = (out_size >= tok_elems + BB * AA)     ? out + tok_elems           : nullptr;
    float* out_a2g  = (out_size >= tok_elems + 2 * BB * AA) ? out + tok_elems + BB * AA : nullptr;

    const int smem_cluster = AA * 32 * 4 + AA * 8 + AA * 4 + AA * 4 + 32 * 4; // 147,584
    const int smem_mlp     = (16384 + 16384 + TM * DD + TM * DD) * 4;         // 163,840

    cudaFuncSetAttribute(cluster_pool_kernel,
                         cudaFuncAttributeMaxDynamicSharedMemorySize, smem_cluster);
    cudaFuncSetAttribute(mlp_kernel,
                         cudaFuncAttributeMaxDynamicSharedMemorySize, smem_mlp);

    cluster_pool_kernel<<<BB, 1024, smem_cluster>>>(emb, coords, mask, out_mask, out_a2g);
    mlp_kernel<<<(BB * AA) / TM, 256, smem_mlp>>>(W1, b1, W2, b2, out);
}

// round 2
// speedup vs baseline: 1.7273x; 1.7273x over previous
#include <cuda_runtime.h>
#include <cstdint>

#define BB 32
#define AA 1024
#define DD 128
#define THR2 0.0025f
#define TM 128   // MLP rows per block

// Scratch (allocation-free rule: __device__ globals)
__device__ float g_sums[BB * AA * DD];   // per-(batch,group) embedding sums
__device__ int   g_cnt[BB * AA];         // per-(batch,group) member counts
__device__ int   g_asg[BB * AA];         // agent -> group

__device__ __forceinline__ float gelu_exact(float x) {
    return 0.5f * x * (1.0f + erff(x * 0.70710678118654752f));
}

// ---------------------------------------------------------------------------
// Kernel 1: per-batch greedy proximity clustering (no pooling here).
// One block of 1024 threads per batch.
// SMEM: adj bitmatrix [A][32] u32 (128KB) + coords (8KB) + assigned (4KB)
//       + cnt (4KB) + valid words (128B) = 147,584 B dynamic.
// ---------------------------------------------------------------------------
__global__ __launch_bounds__(1024, 1)
void cluster_kernel(const float* __restrict__ coords,
                    const int*   __restrict__ mask,
                    float* __restrict__ out_mask,   // may be null
                    float* __restrict__ out_a2g)    // may be null
{
    extern __shared__ unsigned char smem_raw[];
    uint32_t* adj     = (uint32_t*)smem_raw;                       // AA*32 u32
    float2*   sc      = (float2*)(smem_raw + (size_t)AA * 32 * 4); // AA
    int*      s_asg   = (int*)((unsigned char*)sc + AA * 8);       // AA
    int*      s_cnt   = (int*)(s_asg + AA);                        // AA
    uint32_t* s_valid = (uint32_t*)(s_cnt + AA);                   // 32

    const int b   = blockIdx.x;
    const int tid = threadIdx.x;          // 0..1023
    const int w   = tid >> 5;
    const int l   = tid & 31;

    // load coords, init assigned/cnt, validity ballot
    {
        const float2* gc = (const float2*)(coords + (size_t)b * AA * 2);
        sc[tid] = gc[tid];
        s_asg[tid] = -1;
        s_cnt[tid] = 0;
        int v = (mask[(size_t)b * AA + tid] != 0);
        unsigned m = __ballot_sync(0xffffffffu, v);
        if (l == 0) s_valid[w] = m;
    }
    __syncthreads();

    // proximity bit-matrix: warp w owns word w for all rows; cj hoisted.
    {
        const float2 cj = sc[(w << 5) + l];
#pragma unroll 4
        for (int row = 0; row < AA; row++) {
            float2 ci = sc[row];                        // broadcast LDS
            float dx = ci.x - cj.x;
            float dy = ci.y - cj.y;
            float d2 = __fadd_rn(__fmul_rn(dx, dx), __fmul_rn(dy, dy));
            unsigned m = __ballot_sync(0xffffffffu, d2 < THR2);
            if (l == 0) adj[row * 32 + w] = m;
        }
    }
    __syncthreads();

    // greedy scan on warp 0; lane l owns the 32-agent word [l*32, l*32+32).
    if (w == 0) {
        unsigned U = s_valid[l];       // unassigned & valid
        int gid = 0;
        for (int wdi = 0; wdi < 32; wdi++) {
            unsigned Uw = __shfl_sync(0xffffffffu, U, wdi);
            while (Uw) {
                int bit = __ffs(Uw) - 1;
                int i = (wdi << 5) + bit;
                unsigned take = adj[i * 32 + l] & U;   // includes i itself
                U &= ~take;
                unsigned t = take;
                while (t) {
                    int b2 = __ffs(t) - 1;
                    t &= t - 1u;
                    s_asg[(l << 5) + b2] = gid;
                }
                int c = __reduce_add_sync(0xffffffffu, (int)__popc(take));
                if (l == 0) s_cnt[gid] = c;
                gid++;
                Uw = __shfl_sync(0xffffffffu, U, wdi);  // word may have lost bits
            }
        }
    }
    __syncthreads();

    // emit
    {
        int asg = s_asg[tid];
        int cnt = s_cnt[tid];
        g_asg[(size_t)b * AA + tid] = asg;
        g_cnt[(size_t)b * AA + tid] = cnt;
        if (out_a2g)  out_a2g[(size_t)b * AA + tid]  = (float)asg;
        if (out_mask) out_mask[(size_t)b * AA + tid] = (cnt > 0) ? 1.0f : 0.0f;
    }
}

// ---------------------------------------------------------------------------
// Kernel 2: segment-sum pooling via global atomics, 512 blocks of 256 threads.
// Block (c, b): batch b, agents [c*64, c*64+64). Thread: 1 agent x 32 dims.
// ---------------------------------------------------------------------------
__global__ __launch_bounds__(256, 4)
void pool_kernel(const float* __restrict__ emb)
{
    const int b = blockIdx.y;
    const int a = blockIdx.x * 64 + (threadIdx.x >> 2);
    const int g = g_asg[(size_t)b * AA + a];
    if (g < 0) return;

    const int dq = (threadIdx.x & 3) * 32;   // 32-dim slice
    const float4* e = (const float4*)(emb + ((size_t)b * AA + a) * DD + dq);
    float* dst = g_sums + ((size_t)b * AA + g) * DD + dq;

#pragma unroll
    for (int i = 0; i < 8; i++) {
        float4 v = e[i];
        atomicAdd(dst + i * 4 + 0, v.x);
        atomicAdd(dst + i * 4 + 1, v.y);
        atomicAdd(dst + i * 4 + 2, v.z);
        atomicAdd(dst + i * 4 + 3, v.w);
    }
}

// ---------------------------------------------------------------------------
// Kernel 3: tokens = sums / max(cnt,1); out = gelu(tokens@W1+b1)@W2 + b2
// 512 threads, TM=128 rows/block (256 blocks). Weights resident in SMEM.
// 16 warps x 8 rows; lane covers 4 consecutive output columns.
// h reuses the x buffer (accumulators live in regs across the barrier).
// SMEM: W1 64KB + W2 64KB + x/h 64KB = 196,608 B dynamic.
// ---------------------------------------------------------------------------
__global__ __launch_bounds__(512, 1)
void mlp_kernel(const float* __restrict__ W1, const float* __restrict__ b1,
                const float* __restrict__ W2, const float* __restrict__ b2,
                float* __restrict__ out)
{
    extern __shared__ float sm[];
    float* sW1 = sm;            // 16384
    float* sW2 = sm + 16384;    // 16384
    float* sx  = sm + 32768;    // 16384 (x, then reused as h)

    const int tid = threadIdx.x;
    const int rbase = blockIdx.x * TM;

    // stage weights
    {
        const float4* W14 = (const float4*)W1;
        const float4* W24 = (const float4*)W2;
        float4* sW14 = (float4*)sW1;
        float4* sW24 = (float4*)sW2;
#pragma unroll
        for (int i = 0; i < DD * DD / 4 / 512; i++) {
            sW14[tid + i * 512] = W14[tid + i * 512];
            sW24[tid + i * 512] = W24[tid + i * 512];
        }
    }
    // stage x = sums / max(cnt,1)
    {
        const float4* s4 = (const float4*)(g_sums + (size_t)rbase * DD);
        float4* x4 = (float4*)sx;
#pragma unroll
        for (int i = 0; i < TM * DD / 4 / 512; i++) {
            int idx = tid + i * 512;
            int gr = rbase + (idx >> 5);          // 32 float4 per row
            int c = g_cnt[gr];
            float inv = 1.0f / (float)(c > 1 ? c : 1);
            float4 v = s4[idx];
            v.x *= inv; v.y *= inv; v.z *= inv; v.w *= inv;
            x4[idx] = v;
        }
    }
    __syncthreads();

    const int wp   = tid >> 5;
    const int lane = tid & 31;
    const int r0   = wp * 8;      // 8 rows per warp
    const int c0   = lane * 4;    // 4 cols per lane

    float4 acc[8];

    // ---- layer 1 ----
#pragma unroll
    for (int i = 0; i < 8; i++) acc[i] = make_float4(0.f, 0.f, 0.f, 0.f);

#pragma unroll 8
    for (int k = 0; k < DD; k += 4) {
        float4 w0 = *(const float4*)&sW1[(k + 0) * DD + c0];
        float4 w1 = *(const float4*)&sW1[(k + 1) * DD + c0];
        float4 w2 = *(const float4*)&sW1[(k + 2) * DD + c0];
        float4 w3 = *(const float4*)&sW1[(k + 3) * DD + c0];
#pragma unroll
        for (int i = 0; i < 8; i++) {
            float4 xv = *(const float4*)&sx[(r0 + i) * DD + k];   // broadcast
            acc[i].x = fmaf(xv.x, w0.x, acc[i].x);
            acc[i].y = fmaf(xv.x, w0.y, acc[i].y);
            acc[i].z = fmaf(xv.x, w0.z, acc[i].z);
            acc[i].w = fmaf(xv.x, w0.w, acc[i].w);
            acc[i].x = fmaf(xv.y, w1.x, acc[i].x);
            acc[i].y = fmaf(xv.y, w1.y, acc[i].y);
            acc[i].z = fmaf(xv.y, w1.z, acc[i].z);
            acc[i].w = fmaf(xv.y, w1.w, acc[i].w);
            acc[i].x = fmaf(xv.z, w2.x, acc[i].x);
            acc[i].y = fmaf(xv.z, w2.y, acc[i].y);
            acc[i].z = fmaf(xv.z, w2.z, acc[i].z);
            acc[i].w = fmaf(xv.z, w2.w, acc[i].w);
            acc[i].x = fmaf(xv.w, w3.x, acc[i].x);
            acc[i].y = fmaf(xv.w, w3.y, acc[i].y);
            acc[i].z = fmaf(xv.w, w3.z, acc[i].z);
            acc[i].w = fmaf(xv.w, w3.w, acc[i].w);
        }
    }

    {
        float4 bv = *(const float4*)&b1[c0];
#pragma unroll
        for (int i = 0; i < 8; i++) {
            acc[i].x = gelu_exact(acc[i].x + bv.x);
            acc[i].y = gelu_exact(acc[i].y + bv.y);
            acc[i].z = gelu_exact(acc[i].z + bv.z);
            acc[i].w = gelu_exact(acc[i].w + bv.w);
        }
    }
    __syncthreads();   // everyone done reading x
#pragma unroll
    for (int i = 0; i < 8; i++)
        *(float4*)&sx[(r0 + i) * DD + c0] = acc[i];   // x buffer becomes h
    __syncthreads();

    // ---- layer 2 ----
#pragma unroll
    for (int i = 0; i < 8; i++) acc[i] = make_float4(0.f, 0.f, 0.f, 0.f);

#pragma unroll 8
    for (int k = 0; k < DD; k += 4) {
        float4 w0 = *(const float4*)&sW2[(k + 0) * DD + c0];
        float4 w1 = *(const float4*)&sW2[(k + 1) * DD + c0];
        float4 w2 = *(const float4*)&sW2[(k + 2) * DD + c0];
        float4 w3 = *(const float4*)&sW2[(k + 3) * DD + c0];
#pragma unroll
        for (int i = 0; i < 8; i++) {
            float4 hv = *(const float4*)&sx[(r0 + i) * DD + k];
            acc[i].x = fmaf(hv.x, w0.x, acc[i].x);
            acc[i].y = fmaf(hv.x, w0.y, acc[i].y);
            acc[i].z = fmaf(hv.x, w0.z, acc[i].z);
            acc[i].w = fmaf(hv.x, w0.w, acc[i].w);
            acc[i].x = fmaf(hv.y, w1.x, acc[i].x);
            acc[i].y = fmaf(hv.y, w1.y, acc[i].y);
            acc[i].z = fmaf(hv.y, w1.z, acc[i].z);
            acc[i].w = fmaf(hv.y, w1.w, acc[i].w);
            acc[i].x = fmaf(hv.z, w2.x, acc[i].x);
            acc[i].y = fmaf(hv.z, w2.y, acc[i].y);
            acc[i].z = fmaf(hv.z, w2.z, acc[i].z);
            acc[i].w = fmaf(hv.z, w2.w, acc[i].w);
            acc[i].x = fmaf(hv.w, w3.x, acc[i].x);
            acc[i].y = fmaf(hv.w, w3.y, acc[i].y);
            acc[i].z = fmaf(hv.w, w3.z, acc[i].z);
            acc[i].w = fmaf(hv.w, w3.w, acc[i].w);
        }
    }
    {
        float4 bv = *(const float4*)&b2[c0];
#pragma unroll
        for (int i = 0; i < 8; i++) {
            float4 ov;
            ov.x = acc[i].x + bv.x;
            ov.y = acc[i].y + bv.y;
            ov.z = acc[i].z + bv.z;
            ov.w = acc[i].w + bv.w;
            *(float4*)&out[(size_t)(rbase + r0 + i) * DD + c0] = ov;
        }
    }
}

// ---------------------------------------------------------------------------
extern "C" void kernel_launch(void* const* d_in, const int* in_sizes, int n_in,
                              void* d_out, int out_size)
{
    const float* emb    = (const float*)d_in[0];
    const float* coords = (const float*)d_in[1];
    const int*   mask   = (const int*)d_in[2];
    const float* W1     = (const float*)d_in[3];
    const float* b1     = (const float*)d_in[4];
    const float* W2     = (const float*)d_in[5];
    const float* b2     = (const float*)d_in[6];

    float* out = (float*)d_out;
    const int tok_elems = BB * AA * DD;
    float* out_mask = (out_size >= tok_elems + BB * AA)     ? out + tok_elems           : nullptr;
    float* out_a2g  = (out_size >= tok_elems + 2 * BB * AA) ? out + tok_elems + BB * AA : nullptr;

    const int smem_cluster = AA * 32 * 4 + AA * 8 + AA * 4 + AA * 4 + 32 * 4; // 147,584
    const int smem_mlp     = (16384 + 16384 + TM * DD) * 4;                   // 196,608

    cudaFuncSetAttribute(cluster_kernel,
                         cudaFuncAttributeMaxDynamicSharedMemorySize, smem_cluster);
    cudaFuncSetAttribute(mlp_kernel,
                         cudaFuncAttributeMaxDynamicSharedMemorySize, smem_mlp);

    void* sums_ptr = nullptr;
    cudaGetSymbolAddress(&sums_ptr, g_sums);

    cluster_kernel<<<BB, 1024, smem_cluster>>>(coords, mask, out_mask, out_a2g);
    cudaMemsetAsync(sums_ptr, 0, (size_t)BB * AA * DD * sizeof(float));
    pool_kernel<<<dim3(16, BB), 256>>>(emb);
    mlp_kernel<<<(BB * AA) / TM, 512, smem_mlp>>>(W1, b1, W2, b2, out);
}

// round 3
// speedup vs baseline: 2.7563x; 1.5957x over previous
#include <cuda_runtime.h>
#include <cstdint>

#define BB 32
#define AA 1024
#define DD 128
#define THR2 0.0025f
#define TMR 64   // MLP rows per block

typedef unsigned long long u64;

// Scratch (allocation-free rule: __device__ globals)
__device__ float    g_sums[BB * AA * DD];   // per-(batch,group) embedding sums
__device__ int      g_cnt[BB * AA];         // per-(batch,group) member counts
__device__ int      g_asg[BB * AA];         // agent -> group
__device__ uint32_t g_adj[BB * AA * 32];    // proximity bitmatrix (4MB)
__device__ int      g_rowlist[BB * AA];     // compacted nonempty group rows
__device__ int      g_nrows;                // count of nonempty rows

__device__ __forceinline__ float gelu_exact(float x) {
    return 0.5f * x * (1.0f + erff(x * 0.70710678118654752f));
}

// ---------------------------------------------------------------------------
// Kernel 1: adjacency bitmatrix, spread over 8 slices x 32 batches = 256 blocks.
// Warp w computes bit-word w (agents j in [32w,32w+32)) for 128 rows.
// ---------------------------------------------------------------------------
__global__ __launch_bounds__(1024, 2)
void adj_kernel(const float* __restrict__ coords)
{
    __shared__ float2 sc[AA];
    const int b   = blockIdx.y;
    const int tid = threadIdx.x;
    const int w   = tid >> 5;
    const int l   = tid & 31;

    const float2* gc = (const float2*)(coords + (size_t)b * AA * 2);
    sc[tid] = gc[tid];
    __syncthreads();

    const float2 cj = sc[(w << 5) + l];
    const int row0 = blockIdx.x * 128;
    uint32_t* dst = g_adj + ((size_t)b * AA + row0) * 32 + w;

#pragma unroll 4
    for (int r = 0; r < 128; r++) {
        float2 ci = sc[row0 + r];
        float dx = ci.x - cj.x;
        float dy = ci.y - cj.y;
        float d2 = __fadd_rn(__fmul_rn(dx, dx), __fmul_rn(dy, dy));
        unsigned m = __ballot_sync(0xffffffffu, d2 < THR2);
        if (l == 0) dst[(size_t)r * 32] = m;
    }
}

// ---------------------------------------------------------------------------
// Kernel 2: greedy scan per batch (32 blocks x 1024 threads).
// Bulk-loads the 128KB adjacency slice into SMEM, warp 0 runs the greedy scan,
// then the block emits asg/cnt/outputs, compacts nonempty rows, zeroes sums.
// SMEM: adj 128KB + asg 4KB + cnt 4KB + valid 128B = 136,320 B dynamic.
// ---------------------------------------------------------------------------
__global__ __launch_bounds__(1024, 1)
void scan_kernel(const int* __restrict__ mask,
                 float* __restrict__ out_mask,   // may be null
                 float* __restrict__ out_a2g)    // may be null
{
    extern __shared__ unsigned char sraw[];
    uint32_t* adj     = (uint32_t*)sraw;            // AA*32
    int*      s_asg   = (int*)(adj + AA * 32);      // AA
    int*      s_cnt   = s_asg + AA;                 // AA
    uint32_t* s_valid = (uint32_t*)(s_cnt + AA);    // 32

    const int b   = blockIdx.x;
    const int tid = threadIdx.x;
    const int w   = tid >> 5;
    const int l   = tid & 31;

    // bulk load adjacency slice
    {
        const uint4* src = (const uint4*)(g_adj + (size_t)b * AA * 32);
        uint4* dst = (uint4*)adj;
#pragma unroll
        for (int i = 0; i < 8; i++) dst[tid + i * 1024] = src[tid + i * 1024];
    }
    s_asg[tid] = -1;
    s_cnt[tid] = 0;
    {
        int v = (mask[(size_t)b * AA + tid] != 0);
        unsigned m = __ballot_sync(0xffffffffu, v);
        if (l == 0) s_valid[w] = m;
    }
    __syncthreads();

    // greedy scan on warp 0; lane l owns agents [32l, 32l+32)
    if (w == 0) {
        unsigned U = s_valid[l];
        int gid = 0;
        for (int wdi = 0; wdi < 32; wdi++) {
            unsigned Uw = __shfl_sync(0xffffffffu, U, wdi);
            while (Uw) {
                int bit = __ffs(Uw) - 1;
                int i = (wdi << 5) + bit;
                unsigned take = adj[i * 32 + l] & U;   // includes i itself
                U &= ~take;
                unsigned t = take;
                while (t) {
                    int b2 = __ffs(t) - 1;
                    t &= t - 1u;
                    s_asg[(l << 5) + b2] = gid;
                }
                int c = __reduce_add_sync(0xffffffffu, (int)__popc(take));
                if (l == 0) s_cnt[gid] = c;
                gid++;
                Uw = __shfl_sync(0xffffffffu, U, wdi);
            }
        }
    }
    __syncthreads();

    // emit + compact + zero sums for nonempty rows
    {
        int asg = s_asg[tid];
        int cnt = s_cnt[tid];
        g_asg[(size_t)b * AA + tid] = asg;
        g_cnt[(size_t)b * AA + tid] = cnt;
        if (out_a2g)  out_a2g[(size_t)b * AA + tid]  = (float)asg;
        if (out_mask) out_mask[(size_t)b * AA + tid] = (cnt > 0) ? 1.0f : 0.0f;
        if (cnt > 0) {
            int pos = atomicAdd(&g_nrows, 1);
            g_rowlist[pos] = b * AA + tid;
            float4* z = (float4*)(g_sums + (size_t)(b * AA + tid) * DD);
            const float4 zero = make_float4(0.f, 0.f, 0.f, 0.f);
#pragma unroll
            for (int i = 0; i < 32; i++) z[i] = zero;
        }
    }
}

// ---------------------------------------------------------------------------
// Kernel 3: segment-sum pooling via global red ops, 512 blocks of 256 threads.
// ---------------------------------------------------------------------------
__global__ __launch_bounds__(256, 4)
void pool_kernel(const float* __restrict__ emb)
{
    const int b = blockIdx.y;
    const int a = blockIdx.x * 64 + (threadIdx.x >> 2);
    const int g = g_asg[(size_t)b * AA + a];
    if (g < 0) return;

    const int dq = (threadIdx.x & 3) * 32;
    const float4* e = (const float4*)(emb + ((size_t)b * AA + a) * DD + dq);
    float* dst = g_sums + ((size_t)b * AA + g) * DD + dq;

#pragma unroll
    for (int i = 0; i < 8; i++) {
        float4 v = e[i];
        atomicAdd(dst + i * 4 + 0, v.x);
        atomicAdd(dst + i * 4 + 1, v.y);
        atomicAdd(dst + i * 4 + 2, v.z);
        atomicAdd(dst + i * 4 + 3, v.w);
    }
}

// ---------------------------------------------------------------------------
// Kernel 4: fill empty-group rows with the constant row gelu(b1)@W2 + b2.
// 256 blocks x 128 threads; thread = one output column.
// ---------------------------------------------------------------------------
__global__ __launch_bounds__(128, 8)
void fill_kernel(const float* __restrict__ b1, const float* __restrict__ W2,
                 const float* __restrict__ b2, float* __restrict__ out)
{
    __shared__ float gb1[DD];
    __shared__ int scnt[128];
    const int d = threadIdx.x;
    const int row0 = blockIdx.x * 128;

    gb1[d] = gelu_exact(b1[d]);
    scnt[d] = g_cnt[row0 + d];
    __syncthreads();

    float c = b2[d];
#pragma unroll 8
    for (int k = 0; k < DD; k++) c = fmaf(gb1[k], W2[k * DD + d], c);

    for (int r = 0; r < 128; r++)
        if (scnt[r] == 0) out[(size_t)(row0 + r) * DD + d] = c;
}

// ---------------------------------------------------------------------------
// Kernel 5: sparse MLP on compacted nonempty rows.
// 256 threads, TMR=64 rows/block, grid 512 with early exit on g_nrows.
// Weights live in SMEM transposed [c][k] with XOR swizzle (conflict-free
// LDS.128). Inner loop uses packed fma.rn.f32x2 (2 FMA/instr).
// Each warp owns 8 rows exclusively -> no barriers between layers.
// SMEM: W1T 64KB + W2T 64KB + x/h 32KB + rowlist = 164,608 B dynamic.
// ---------------------------------------------------------------------------
__global__ __launch_bounds__(256, 1)
void mlp_kernel(const float* __restrict__ W1, const float* __restrict__ b1,
                const float* __restrict__ W2, const float* __restrict__ b2,
                float* __restrict__ out)
{
    const int n = g_nrows;
    const int base = blockIdx.x * TMR;
    if (base >= n) return;

    extern __shared__ float sm[];
    float* sW1T = sm;                 // 16384 floats (4096 float4 slots)
    float* sW2T = sm + 16384;         // 16384
    float* sx   = sm + 32768;         // TMR*DD = 8192
    int*   srid = (int*)(sm + 40960); // TMR

    const int tid = threadIdx.x;

    // stage transposed + swizzled weights: slot(c,g) = c*32 + (g ^ ((c>>2)&7))
    {
        float4* w1t = (float4*)sW1T;
        float4* w2t = (float4*)sW2T;
#pragma unroll
        for (int it = 0; it < 16; it++) {
            int i = tid + it * 256;
            int c = i & 127, g = i >> 7;
            int slot = c * 32 + (g ^ ((c >> 2) & 7));
            float4 v1, v2;
            v1.x = W1[(4 * g + 0) * DD + c];
            v1.y = W1[(4 * g + 1) * DD + c];
            v1.z = W1[(4 * g + 2) * DD + c];
            v1.w = W1[(4 * g + 3) * DD + c];
            v2.x = W2[(4 * g + 0) * DD + c];
            v2.y = W2[(4 * g + 1) * DD + c];
            v2.z = W2[(4 * g + 2) * DD + c];
            v2.w = W2[(4 * g + 3) * DD + c];
            w1t[slot] = v1;
            w2t[slot] = v2;
        }
    }
    // row id list (clamped for padded rows)
    if (tid < TMR) {
        int idx = base + tid;
        srid[tid] = g_rowlist[idx < n ? idx : n - 1];
    }
    __syncthreads();

    // stage x = sums / max(cnt,1)
    {
        float4* x4 = (float4*)sx;
#pragma unroll
        for (int it = 0; it < TMR * 32 / 256; it++) {
            int i = tid + it * 256;
            int r = i >> 5, q = i & 31;
            int gr = srid[r];
            int c = g_cnt[gr];
            float inv = 1.0f / (float)(c > 1 ? c : 1);
            float4 v = *((const float4*)(g_sums + (size_t)gr * DD) + q);
            v.x *= inv; v.y *= inv; v.z *= inv; v.w *= inv;
            x4[i] = v;
        }
    }
    __syncthreads();

    const int wp   = tid >> 5;
    const int lane = tid & 31;
    const int r0   = wp * 8;        // 8 rows per warp (8 warps * 8 = 64)
    const int c0   = lane * 4;      // 4 cols per lane
    const int swl  = lane & 7;

    u64 acc[8][4];

    // ================= layer 1 =================
#pragma unroll
    for (int r = 0; r < 8; r++)
#pragma unroll
        for (int cc = 0; cc < 4; cc++) acc[r][cc] = 0ull;

    {
        const ulonglong2* wp4 = (const ulonglong2*)sW1T;
#pragma unroll 2
        for (int g = 0; g < 32; g++) {
            const int gs = g ^ swl;
            ulonglong2 wv0 = wp4[(c0 + 0) * 32 + gs];
            ulonglong2 wv1 = wp4[(c0 + 1) * 32 + gs];
            ulonglong2 wv2 = wp4[(c0 + 2) * 32 + gs];
            ulonglong2 wv3 = wp4[(c0 + 3) * 32 + gs];
#pragma unroll
            for (int r = 0; r < 8; r++) {
                ulonglong2 xv = *(const ulonglong2*)(sx + (r0 + r) * DD + 4 * g);
                asm("fma.rn.f32x2 %0, %1, %2, %0;" : "+l"(acc[r][0]) : "l"(xv.x), "l"(wv0.x));
                asm("fma.rn.f32x2 %0, %1, %2, %0;" : "+l"(acc[r][1]) : "l"(xv.x), "l"(wv1.x));
                asm("fma.rn.f32x2 %0, %1, %2, %0;" : "+l"(acc[r][2]) : "l"(xv.x), "l"(wv2.x));
                asm("fma.rn.f32x2 %0, %1, %2, %0;" : "+l"(acc[r][3]) : "l"(xv.x), "l"(wv3.x));
                asm("fma.rn.f32x2 %0, %1, %2, %0;" : "+l"(acc[r][0]) : "l"(xv.y), "l"(wv0.y));
                asm("fma.rn.f32x2 %0, %1, %2, %0;" : "+l"(acc[r][1]) : "l"(xv.y), "l"(wv1.y));
                asm("fma.rn.f32x2 %0, %1, %2, %0;" : "+l"(acc[r][2]) : "l"(xv.y), "l"(wv2.y));
                asm("fma.rn.f32x2 %0, %1, %2, %0;" : "+l"(acc[r][3]) : "l"(xv.y), "l"(wv3.y));
            }
        }
    }
    // epilogue 1: h = gelu(lo+hi + b1); warp owns its rows -> no barrier
    {
        float4 bv = *(const float4*)&b1[c0];
#pragma unroll
        for (int r = 0; r < 8; r++) {
            float4 h;
            h.x = gelu_exact(__uint_as_float((unsigned)acc[r][0]) + __uint_as_float((unsigned)(acc[r][0] >> 32)) + bv.x);
            h.y = gelu_exact(__uint_as_float((unsigned)acc[r][1]) + __uint_as_float((unsigned)(acc[r][1] >> 32)) + bv.y);
            h.z = gelu_exact(__uint_as_float((unsigned)acc[r][2]) + __uint_as_float((unsigned)(acc[r][2] >> 32)) + bv.z);
            h.w = gelu_exact(__uint_as_float((unsigned)acc[r][3]) + __uint_as_float((unsigned)(acc[r][3] >> 32)) + bv.w);
            *(float4*)&sx[(r0 + r) * DD + c0] = h;
        }
    }
    __syncwarp();

    // ================= layer 2 =================
#pragma unroll
    for (int r = 0; r < 8; r++)
#pragma unroll
        for (int cc = 0; cc < 4; cc++) acc[r][cc] = 0ull;

    {
        const ulonglong2* wp4 = (const ulonglong2*)sW2T;
#pragma unroll 2
        for (int g = 0; g < 32; g++) {
            const int gs = g ^ swl;
            ulonglong2 wv0 = wp4[(c0 + 0) * 32 + gs];
            ulonglong2 wv1 = wp4[(c0 + 1) * 32 + gs];
            ulonglong2 wv2 = wp4[(c0 + 2) * 32 + gs];
            ulonglong2 wv3 = wp4[(c0 + 3) * 32 + gs];
#pragma unroll
            for (int r = 0; r < 8; r++) {
                ulonglong2 xv = *(const ulonglong2*)(sx + (r0 + r) * DD + 4 * g);
                asm("fma.rn.f32x2 %0, %1, %2, %0;" : "+l"(acc[r][0]) : "l"(xv.x), "l"(wv0.x));
                asm("fma.rn.f32x2 %0, %1, %2, %0;" : "+l"(acc[r][1]) : "l"(xv.x), "l"(wv1.x));
                asm("fma.rn.f32x2 %0, %1, %2, %0;" : "+l"(acc[r][2]) : "l"(xv.x), "l"(wv2.x));
                asm("fma.rn.f32x2 %0, %1, %2, %0;" : "+l"(acc[r][3]) : "l"(xv.x), "l"(wv3.x));
                asm("fma.rn.f32x2 %0, %1, %2, %0;" : "+l"(acc[r][0]) : "l"(xv.y), "l"(wv0.y));
                asm("fma.rn.f32x2 %0, %1, %2, %0;" : "+l"(acc[r][1]) : "l"(xv.y), "l"(wv1.y));
                asm("fma.rn.f32x2 %0, %1, %2, %0;" : "+l"(acc[r][2]) : "l"(xv.y), "l"(wv2.y));
                asm("fma.rn.f32x2 %0, %1, %2, %0;" : "+l"(acc[r][3]) : "l"(xv.y), "l"(wv3.y));
            }
        }
    }
    // epilogue 2: out = lo+hi + b2, scatter to real rows
    {
        float4 bv = *(const float4*)&b2[c0];
#pragma unroll
        for (int r = 0; r < 8; r++) {
            int idx = base + r0 + r;
            if (idx < n) {
                int gr = srid[r0 + r];
                float4 ov;
                ov.x = __uint_as_float((unsigned)acc[r][0]) + __uint_as_float((unsigned)(acc[r][0] >> 32)) + bv.x;
                ov.y = __uint_as_float((unsigned)acc[r][1]) + __uint_as_float((unsigned)(acc[r][1] >> 32)) + bv.y;
                ov.z = __uint_as_float((unsigned)acc[r][2]) + __uint_as_float((unsigned)(acc[r][2] >> 32)) + bv.z;
                ov.w = __uint_as_float((unsigned)acc[r][3]) + __uint_as_float((unsigned)(acc[r][3] >> 32)) + bv.w;
                *(float4*)&out[(size_t)gr * DD + c0] = ov;
            }
        }
    }
}

// ---------------------------------------------------------------------------
extern "C" void kernel_launch(void* const* d_in, const int* in_sizes, int n_in,
                              void* d_out, int out_size)
{
    const float* emb    = (const float*)d_in[0];
    const float* coords = (const float*)d_in[1];
    const int*   mask   = (const int*)d_in[2];
    const float* W1     = (const float*)d_in[3];
    const float* b1     = (const float*)d_in[4];
    const float* W2     = (const float*)d_in[5];
    const float* b2     = (const float*)d_in[6];

    float* out = (float*)d_out;
    const int tok_elems = BB * AA * DD;
    float* out_mask = (out_size >= tok_elems + BB * AA)     ? out + tok_elems           : nullptr;
    float* out_a2g  = (out_size >= tok_elems + 2 * BB * AA) ? out + tok_elems + BB * AA : nullptr;

    const int smem_scan = AA * 32 * 4 + AA * 4 + AA * 4 + 32 * 4;           // 139,392
    const int smem_mlp  = (16384 + 16384 + TMR * DD) * 4 + TMR * 4 + 256;   // ~164,864

    cudaFuncSetAttribute(scan_kernel,
                         cudaFuncAttributeMaxDynamicSharedMemorySize, smem_scan);
    cudaFuncSetAttribute(mlp_kernel,
                         cudaFuncAttributeMaxDynamicSharedMemorySize, smem_mlp);

    void* nrows_ptr = nullptr;
    cudaGetSymbolAddress(&nrows_ptr, g_nrows);

    cudaMemsetAsync(nrows_ptr, 0, sizeof(int));
    adj_kernel<<<dim3(8, BB), 1024>>>(coords);
    scan_kernel<<<BB, 1024, smem_scan>>>(mask, out_mask, out_a2g);
    fill_kernel<<<256, 128>>>(b1, W2, b2, out);
    pool_kernel<<<dim3(16, BB), 256>>>(emb);
    mlp_kernel<<<(BB * AA) / TMR, 256, smem_mlp>>>(W1, b1, W2, b2, out);
}

// round 4
// speedup vs baseline: 3.1692x; 1.1498x over previous
#include <cuda_runtime.h>
#include <cstdint>

#define BB 32
#define AA 1024
#define DD 128
#define THR2 0.0025f
#define TMR 64   // MLP rows per block

typedef unsigned long long u64;

// Scratch (allocation-free rule: __device__ globals)
__device__ int      g_cnt[BB * AA];         // per-(batch,group) member counts
__device__ int      g_asg[BB * AA];         // agent -> group
__device__ uint32_t g_adj[BB * AA * 32];    // proximity bitmatrix (4MB)
__device__ uint32_t g_members[BB * AA * 32];// per-group member bitmask (4MB)
__device__ int      g_rowlist[BB * AA];     // compacted nonempty group rows
__device__ int      g_nrows;                // count of nonempty rows

__device__ __forceinline__ float gelu_exact(float x) {
    return 0.5f * x * (1.0f + erff(x * 0.70710678118654752f));
}

// ---------------------------------------------------------------------------
// Kernel 1: adjacency bitmatrix, 8 slices x 32 batches = 256 blocks.
// Warp w computes bit-word w (agents j in [32w,32w+32)) for 128 rows.
// ---------------------------------------------------------------------------
__global__ __launch_bounds__(1024, 2)
void adj_kernel(const float* __restrict__ coords)
{
    __shared__ float2 sc[AA];
    const int b   = blockIdx.y;
    const int tid = threadIdx.x;
    const int w   = tid >> 5;
    const int l   = tid & 31;

    const float2* gc = (const float2*)(coords + (size_t)b * AA * 2);
    sc[tid] = gc[tid];
    __syncthreads();

    const float2 cj = sc[(w << 5) + l];
    const int row0 = blockIdx.x * 128;
    uint32_t* dst = g_adj + ((size_t)b * AA + row0) * 32 + w;

#pragma unroll 4
    for (int r = 0; r < 128; r++) {
        float2 ci = sc[row0 + r];
        float dx = ci.x - cj.x;
        float dy = ci.y - cj.y;
        float d2 = __fadd_rn(__fmul_rn(dx, dx), __fmul_rn(dy, dy));
        unsigned m = __ballot_sync(0xffffffffu, d2 < THR2);
        if (l == 0) dst[(size_t)r * 32] = m;
    }
}

// ---------------------------------------------------------------------------
// Kernel 2: greedy scan per batch (32 blocks x 1024 threads).
// Bulk-loads the 128KB adjacency slice into SMEM, warp 0 runs the scan and
// stores each group's member bitmask, then the block emits outputs/compaction.
// SMEM: adj 128KB + asg 4KB + cnt 4KB + valid 128B = 136,320 B dynamic.
// ---------------------------------------------------------------------------
__global__ __launch_bounds__(1024, 1)
void scan_kernel(const int* __restrict__ mask,
                 float* __restrict__ out_mask,   // may be null
                 float* __restrict__ out_a2g)    // may be null
{
    extern __shared__ unsigned char sraw[];
    uint32_t* adj     = (uint32_t*)sraw;            // AA*32
    int*      s_asg   = (int*)(adj + AA * 32);      // AA
    int*      s_cnt   = s_asg + AA;                 // AA
    uint32_t* s_valid = (uint32_t*)(s_cnt + AA);    // 32

    const int b   = blockIdx.x;
    const int tid = threadIdx.x;
    const int w   = tid >> 5;
    const int l   = tid & 31;

    // bulk load adjacency slice
    {
        const uint4* src = (const uint4*)(g_adj + (size_t)b * AA * 32);
        uint4* dst = (uint4*)adj;
#pragma unroll
        for (int i = 0; i < 8; i++) dst[tid + i * 1024] = src[tid + i * 1024];
    }
    s_asg[tid] = -1;
    s_cnt[tid] = 0;
    {
        int v = (mask[(size_t)b * AA + tid] != 0);
        unsigned m = __ballot_sync(0xffffffffu, v);
        if (l == 0) s_valid[w] = m;
    }
    __syncthreads();

    // greedy scan on warp 0; lane l owns agents [32l, 32l+32)
    if (w == 0) {
        uint32_t* memb = g_members + ((size_t)b << 10) * 32;
        unsigned U = s_valid[l];
        int gid = 0;
        for (int wdi = 0; wdi < 32; wdi++) {
            unsigned Uw = __shfl_sync(0xffffffffu, U, wdi);
            while (Uw) {
                int bit = __ffs(Uw) - 1;
                int i = (wdi << 5) + bit;
                unsigned take = adj[i * 32 + l] & U;   // includes i itself
                U &= ~take;
                memb[gid * 32 + l] = take;             // member bitmask word l
                unsigned t = take;
                while (t) {
                    int b2 = __ffs(t) - 1;
                    t &= t - 1u;
                    s_asg[(l << 5) + b2] = gid;
                }
                int c = __reduce_add_sync(0xffffffffu, (int)__popc(take));
                if (l == 0) s_cnt[gid] = c;
                gid++;
                Uw = __shfl_sync(0xffffffffu, U, wdi);
            }
        }
    }
    __syncthreads();

    // emit + compact
    {
        int asg = s_asg[tid];
        int cnt = s_cnt[tid];
        g_asg[(size_t)b * AA + tid] = asg;
        g_cnt[(size_t)b * AA + tid] = cnt;
        if (out_a2g)  out_a2g[(size_t)b * AA + tid]  = (float)asg;
        if (out_mask) out_mask[(size_t)b * AA + tid] = (cnt > 0) ? 1.0f : 0.0f;
        if (cnt > 0) {
            int pos = atomicAdd(&g_nrows, 1);
            g_rowlist[pos] = b * AA + tid;
        }
    }
}

// ---------------------------------------------------------------------------
// Kernel 3: fill empty-group rows with the constant row gelu(b1)@W2 + b2.
// 256 blocks x 128 threads; thread = one output column.
// ---------------------------------------------------------------------------
__global__ __launch_bounds__(128, 8)
void fill_kernel(const float* __restrict__ b1, const float* __restrict__ W2,
                 const float* __restrict__ b2, float* __restrict__ out)
{
    __shared__ float gb1[DD];
    __shared__ int scnt[128];
    const int d = threadIdx.x;
    const int row0 = blockIdx.x * 128;

    gb1[d] = gelu_exact(b1[d]);
    scnt[d] = g_cnt[row0 + d];
    __syncthreads();

    float c = b2[d];
#pragma unroll 8
    for (int k = 0; k < DD; k++) c = fmaf(gb1[k], W2[k * DD + d], c);

    for (int r = 0; r < 128; r++)
        if (scnt[r] == 0) out[(size_t)(row0 + r) * DD + d] = c;
}

// ---------------------------------------------------------------------------
// Kernel 4: sparse MLP on compacted nonempty rows, pooling fused into
// x-staging via member-mask gather (no atomics, no g_sums).
// 256 threads, TMR=64 rows/block, grid 512 with early exit on g_nrows.
// Weights in SMEM transposed [c][k] with XOR swizzle (conflict-free LDS.128).
// Inner loop uses packed fma.rn.f32x2 (2 FMA/instr).
// Each warp owns 8 rows exclusively (stages and computes the same rows).
// SMEM: W1T 64KB + W2T 64KB + x/h 32KB + rowlist = ~164.9KB dynamic.
// ---------------------------------------------------------------------------
__global__ __launch_bounds__(256, 1)
void mlp_kernel(const float* __restrict__ emb,
                const float* __restrict__ W1, const float* __restrict__ b1,
                const float* __restrict__ W2, const float* __restrict__ b2,
                float* __restrict__ out)
{
    const int n = g_nrows;
    const int base = blockIdx.x * TMR;
    if (base >= n) return;

    extern __shared__ float sm[];
    float* sW1T = sm;                 // 16384 floats (4096 float4 slots)
    float* sW2T = sm + 16384;         // 16384
    float* sx   = sm + 32768;         // TMR*DD = 8192
    int*   srid = (int*)(sm + 40960); // TMR

    const int tid  = threadIdx.x;
    const int wp   = tid >> 5;
    const int lane = tid & 31;
    const int r0   = wp * 8;        // 8 rows per warp (8 warps * 8 = 64)
    const int c0   = lane * 4;      // 4 cols per lane
    const int swl  = lane & 7;

    // row id list (clamped for padded rows)
    if (tid < TMR) {
        int idx = base + tid;
        srid[tid] = g_rowlist[idx < n ? idx : n - 1];
    }

    // stage transposed + swizzled weights: slot(c,g) = c*32 + (g ^ ((c>>2)&7))
    {
        float4* w1t = (float4*)sW1T;
        float4* w2t = (float4*)sW2T;
#pragma unroll
        for (int it = 0; it < 16; it++) {
            int i = tid + it * 256;
            int c = i & 127, g = i >> 7;
            int slot = c * 32 + (g ^ ((c >> 2) & 7));
            float4 v1, v2;
            v1.x = W1[(4 * g + 0) * DD + c];
            v1.y = W1[(4 * g + 1) * DD + c];
            v1.z = W1[(4 * g + 2) * DD + c];
            v1.w = W1[(4 * g + 3) * DD + c];
            v2.x = W2[(4 * g + 0) * DD + c];
            v2.y = W2[(4 * g + 1) * DD + c];
            v2.z = W2[(4 * g + 2) * DD + c];
            v2.w = W2[(4 * g + 3) * DD + c];
            w1t[slot] = v1;
            w2t[slot] = v2;
        }
    }
    __syncthreads();   // srid visible (weights barrier shared)

    // stage x rows r0..r0+7: gather member rows of each group, mean in regs.
    // lane covers dims [4*lane, 4*lane+4).
#pragma unroll 1
    for (int r = r0; r < r0 + 8; r++) {
        const int gr = srid[r];
        const unsigned mw = g_members[(size_t)gr * 32 + lane];
        unsigned nz = __ballot_sync(0xffffffffu, mw != 0);
        const float* ebase = emb + (size_t)(gr & ~(AA - 1)) * DD;  // batch base
        float4 a4 = make_float4(0.f, 0.f, 0.f, 0.f);
        while (nz) {
            int w2i = __ffs(nz) - 1;
            nz &= nz - 1u;
            unsigned m = __shfl_sync(0xffffffffu, mw, w2i);
            while (m) {
                int bit = __ffs(m) - 1;
                m &= m - 1u;
                float4 v = *((const float4*)(ebase + (size_t)((w2i << 5) + bit) * DD) + lane);
                a4.x += v.x; a4.y += v.y; a4.z += v.z; a4.w += v.w;
            }
        }
        int c = __reduce_add_sync(0xffffffffu, (int)__popc(mw));
        float inv = 1.0f / (float)(c > 1 ? c : 1);
        a4.x *= inv; a4.y *= inv; a4.z *= inv; a4.w *= inv;
        *(float4*)&sx[r * DD + c0] = a4;
    }
    __syncwarp();   // warp owns its rows; x within-warp visible

    u64 acc[8][4];

    // ================= layer 1 =================
#pragma unroll
    for (int r = 0; r < 8; r++)
#pragma unroll
        for (int cc = 0; cc < 4; cc++) acc[r][cc] = 0ull;

    {
        const ulonglong2* wp4 = (const ulonglong2*)sW1T;
#pragma unroll 2
        for (int g = 0; g < 32; g++) {
            const int gs = g ^ swl;
            ulonglong2 wv0 = wp4[(c0 + 0) * 32 + gs];
            ulonglong2 wv1 = wp4[(c0 + 1) * 32 + gs];
            ulonglong2 wv2 = wp4[(c0 + 2) * 32 + gs];
            ulonglong2 wv3 = wp4[(c0 + 3) * 32 + gs];
#pragma unroll
            for (int r = 0; r < 8; r++) {
                ulonglong2 xv = *(const ulonglong2*)(sx + (r0 + r) * DD + 4 * g);
                asm("fma.rn.f32x2 %0, %1, %2, %0;" : "+l"(acc[r][0]) : "l"(xv.x), "l"(wv0.x));
                asm("fma.rn.f32x2 %0, %1, %2, %0;" : "+l"(acc[r][1]) : "l"(xv.x), "l"(wv1.x));
                asm("fma.rn.f32x2 %0, %1, %2, %0;" : "+l"(acc[r][2]) : "l"(xv.x), "l"(wv2.x));
                asm("fma.rn.f32x2 %0, %1, %2, %0;" : "+l"(acc[r][3]) : "l"(xv.x), "l"(wv3.x));
                asm("fma.rn.f32x2 %0, %1, %2, %0;" : "+l"(acc[r][0]) : "l"(xv.y), "l"(wv0.y));
                asm("fma.rn.f32x2 %0, %1, %2, %0;" : "+l"(acc[r][1]) : "l"(xv.y), "l"(wv1.y));
                asm("fma.rn.f32x2 %0, %1, %2, %0;" : "+l"(acc[r][2]) : "l"(xv.y), "l"(wv2.y));
                asm("fma.rn.f32x2 %0, %1, %2, %0;" : "+l"(acc[r][3]) : "l"(xv.y), "l"(wv3.y));
            }
        }
    }
    // epilogue 1: h = gelu(lo+hi + b1); warp owns its rows -> no barrier
    {
        float4 bv = *(const float4*)&b1[c0];
#pragma unroll
        for (int r = 0; r < 8; r++) {
            float4 h;
            h.x = gelu_exact(__uint_as_float((unsigned)acc[r][0]) + __uint_as_float((unsigned)(acc[r][0] >> 32)) + bv.x);
            h.y = gelu_exact(__uint_as_float((unsigned)acc[r][1]) + __uint_as_float((unsigned)(acc[r][1] >> 32)) + bv.y);
            h.z = gelu_exact(__uint_as_float((unsigned)acc[r][2]) + __uint_as_float((unsigned)(acc[r][2] >> 32)) + bv.z);
            h.w = gelu_exact(__uint_as_float((unsigned)acc[r][3]) + __uint_as_float((unsigned)(acc[r][3] >> 32)) + bv.w);
            *(float4*)&sx[(r0 + r) * DD + c0] = h;
        }
    }
    __syncwarp();

    // ================= layer 2 =================
#pragma unroll
    for (int r = 0; r < 8; r++)
#pragma unroll
        for (int cc = 0; cc < 4; cc++) acc[r][cc] = 0ull;

    {
        const ulonglong2* wp4 = (const ulonglong2*)sW2T;
#pragma unroll 2
        for (int g = 0; g < 32; g++) {
            const int gs = g ^ swl;
            ulonglong2 wv0 = wp4[(c0 + 0) * 32 + gs];
            ulonglong2 wv1 = wp4[(c0 + 1) * 32 + gs];
            ulonglong2 wv2 = wp4[(c0 + 2) * 32 + gs];
            ulonglong2 wv3 = wp4[(c0 + 3) * 32 + gs];
#pragma unroll
            for (int r = 0; r < 8; r++) {
                ulonglong2 xv = *(const ulonglong2*)(sx + (r0 + r) * DD + 4 * g);
                asm("fma.rn.f32x2 %0, %1, %2, %0;" : "+l"(acc[r][0]) : "l"(xv.x), "l"(wv0.x));
                asm("fma.rn.f32x2 %0, %1, %2, %0;" : "+l"(acc[r][1]) : "l"(xv.x), "l"(wv1.x));
                asm("fma.rn.f32x2 %0, %1, %2, %0;" : "+l"(acc[r][2]) : "l"(xv.x), "l"(wv2.x));
                asm("fma.rn.f32x2 %0, %1, %2, %0;" : "+l"(acc[r][3]) : "l"(xv.x), "l"(wv3.x));
                asm("fma.rn.f32x2 %0, %1, %2, %0;" : "+l"(acc[r][0]) : "l"(xv.y), "l"(wv0.y));
                asm("fma.rn.f32x2 %0, %1, %2, %0;" : "+l"(acc[r][1]) : "l"(xv.y), "l"(wv1.y));
                asm("fma.rn.f32x2 %0, %1, %2, %0;" : "+l"(acc[r][2]) : "l"(xv.y), "l"(wv2.y));
                asm("fma.rn.f32x2 %0, %1, %2, %0;" : "+l"(acc[r][3]) : "l"(xv.y), "l"(wv3.y));
            }
        }
    }
    // epilogue 2: out = lo+hi + b2, scatter to real rows
    {
        float4 bv = *(const float4*)&b2[c0];
#pragma unroll
        for (int r = 0; r < 8; r++) {
            int idx = base + r0 + r;
            if (idx < n) {
                int gr = srid[r0 + r];
                float4 ov;
                ov.x = __uint_as_float((unsigned)acc[r][0]) + __uint_as_float((unsigned)(acc[r][0] >> 32)) + bv.x;
                ov.y = __uint_as_float((unsigned)acc[r][1]) + __uint_as_float((unsigned)(acc[r][1] >> 32)) + bv.y;
                ov.z = __uint_as_float((unsigned)acc[r][2]) + __uint_as_float((unsigned)(acc[r][2] >> 32)) + bv.z;
                ov.w = __uint_as_float((unsigned)acc[r][3]) + __uint_as_float((unsigned)(acc[r][3] >> 32)) + bv.w;
                *(float4*)&out[(size_t)gr * DD + c0] = ov;
            }
        }
    }
}

// ---------------------------------------------------------------------------
extern "C" void kernel_launch(void* const* d_in, const int* in_sizes, int n_in,
                              void* d_out, int out_size)
{
    const float* emb    = (const float*)d_in[0];
    const float* coords = (const float*)d_in[1];
    const int*   mask   = (const int*)d_in[2];
    const float* W1     = (const float*)d_in[3];
    const float* b1     = (const float*)d_in[4];
    const float* W2     = (const float*)d_in[5];
    const float* b2     = (const float*)d_in[6];

    float* out = (float*)d_out;
    const int tok_elems = BB * AA * DD;
    float* out_mask = (out_size >= tok_elems + BB * AA)     ? out + tok_elems           : nullptr;
    float* out_a2g  = (out_size >= tok_elems + 2 * BB * AA) ? out + tok_elems + BB * AA : nullptr;

    const int smem_scan = AA * 32 * 4 + AA * 4 + AA * 4 + 32 * 4;           // 139,392
    const int smem_mlp  = (16384 + 16384 + TMR * DD) * 4 + TMR * 4 + 256;   // ~164,864

    cudaFuncSetAttribute(scan_kernel,
                         cudaFuncAttributeMaxDynamicSharedMemorySize, smem_scan);
    cudaFuncSetAttribute(mlp_kernel,
                         cudaFuncAttributeMaxDynamicSharedMemorySize, smem_mlp);

    void* nrows_ptr = nullptr;
    cudaGetSymbolAddress(&nrows_ptr, g_nrows);

    cudaMemsetAsync(nrows_ptr, 0, sizeof(int));
    adj_kernel<<<dim3(8, BB), 1024>>>(coords);
    scan_kernel<<<BB, 1024, smem_scan>>>(mask, out_mask, out_a2g);
    fill_kernel<<<256, 128>>>(b1, W2, b2, out);
    mlp_kernel<<<(BB * AA) / TMR, 256, smem_mlp>>>(emb, W1, b1, W2, b2, out);
}

// round 5
// speedup vs baseline: 3.7374x; 1.1793x over previous
#include <cuda_runtime.h>
#include <cstdint>

#define BB 32
#define AA 1024
#define DD 128
#define THR2 0.0025f
#define TMR 64   // MLP rows per block

typedef unsigned long long u64;

// Scratch (allocation-free rule: __device__ globals)
__device__ int      g_cnt[BB * AA];         // per-(batch,group) member counts
__device__ int      g_asg[BB * AA];         // agent -> group
__device__ uint32_t g_adj[BB * AA * 32];    // proximity bitmatrix (4MB)
__device__ uint32_t g_members[BB * AA * 32];// per-group member bitmask (4MB)
__device__ int      g_rowlist[BB * AA];     // compacted nonempty group rows
__device__ int      g_nrows;                // count of nonempty rows

__device__ __forceinline__ float gelu_exact(float x) {
    return 0.5f * x * (1.0f + erff(x * 0.70710678118654752f));
}

// ---------------------------------------------------------------------------
// Kernel 1: adjacency bitmatrix, 8 slices x 32 batches = 256 blocks.
// Warp w computes bit-word w (agents j in [32w,32w+32)) for 128 rows.
// ---------------------------------------------------------------------------
__global__ __launch_bounds__(1024, 2)
void adj_kernel(const float* __restrict__ coords)
{
    __shared__ float2 sc[AA];
    const int b   = blockIdx.y;
    const int tid = threadIdx.x;
    const int w   = tid >> 5;
    const int l   = tid & 31;

    const float2* gc = (const float2*)(coords + (size_t)b * AA * 2);
    sc[tid] = gc[tid];
    __syncthreads();

    const float2 cj = sc[(w << 5) + l];
    const int row0 = blockIdx.x * 128;
    uint32_t* dst = g_adj + ((size_t)b * AA + row0) * 32 + w;

#pragma unroll 4
    for (int r = 0; r < 128; r++) {
        float2 ci = sc[row0 + r];
        float dx = ci.x - cj.x;
        float dy = ci.y - cj.y;
        float d2 = __fadd_rn(__fmul_rn(dx, dx), __fmul_rn(dy, dy));
        unsigned m = __ballot_sync(0xffffffffu, d2 < THR2);
        if (l == 0) dst[(size_t)r * 32] = m;
    }
}

// ---------------------------------------------------------------------------
// Kernel 2: greedy scan per batch (32 blocks x 1024 threads).
// Bulk-loads the 128KB adjacency slice into SMEM, warp 0 runs the scan and
// stores each group's member bitmask, then the block emits outputs/compaction.
// SMEM: adj 128KB + asg 4KB + cnt 4KB + valid 128B = 136,320 B dynamic.
// ---------------------------------------------------------------------------
__global__ __launch_bounds__(1024, 1)
void scan_kernel(const int* __restrict__ mask,
                 float* __restrict__ out_mask,   // may be null
                 float* __restrict__ out_a2g)    // may be null
{
    extern __shared__ unsigned char sraw[];
    uint32_t* adj     = (uint32_t*)sraw;            // AA*32
    int*      s_asg   = (int*)(adj + AA * 32);      // AA
    int*      s_cnt   = s_asg + AA;                 // AA
    uint32_t* s_valid = (uint32_t*)(s_cnt + AA);    // 32

    const int b   = blockIdx.x;
    const int tid = threadIdx.x;
    const int w   = tid >> 5;
    const int l   = tid & 31;

    // bulk load adjacency slice
    {
        const uint4* src = (const uint4*)(g_adj + (size_t)b * AA * 32);
        uint4* dst = (uint4*)adj;
#pragma unroll
        for (int i = 0; i < 8; i++) dst[tid + i * 1024] = src[tid + i * 1024];
    }
    s_asg[tid] = -1;
    s_cnt[tid] = 0;
    {
        int v = (mask[(size_t)b * AA + tid] != 0);
        unsigned m = __ballot_sync(0xffffffffu, v);
        if (l == 0) s_valid[w] = m;
    }
    __syncthreads();

    // greedy scan on warp 0; lane l owns agents [32l, 32l+32)
    if (w == 0) {
        uint32_t* memb = g_members + ((size_t)b << 10) * 32;
        unsigned U = s_valid[l];
        int gid = 0;
        for (int wdi = 0; wdi < 32; wdi++) {
            unsigned Uw = __shfl_sync(0xffffffffu, U, wdi);
            while (Uw) {
                int bit = __ffs(Uw) - 1;
                int i = (wdi << 5) + bit;
                unsigned take = adj[i * 32 + l] & U;   // includes i itself
                U &= ~take;
                memb[gid * 32 + l] = take;             // member bitmask word l
                unsigned t = take;
                while (t) {
                    int b2 = __ffs(t) - 1;
                    t &= t - 1u;
                    s_asg[(l << 5) + b2] = gid;
                }
                int c = __reduce_add_sync(0xffffffffu, (int)__popc(take));
                if (l == 0) s_cnt[gid] = c;
                gid++;
                Uw = __shfl_sync(0xffffffffu, U, wdi);
            }
        }
    }
    __syncthreads();

    // emit + compact
    {
        int asg = s_asg[tid];
        int cnt = s_cnt[tid];
        g_asg[(size_t)b * AA + tid] = asg;
        g_cnt[(size_t)b * AA + tid] = cnt;
        if (out_a2g)  out_a2g[(size_t)b * AA + tid]  = (float)asg;
        if (out_mask) out_mask[(size_t)b * AA + tid] = (cnt > 0) ? 1.0f : 0.0f;
        if (cnt > 0) {
            int pos = atomicAdd(&g_nrows, 1);
            g_rowlist[pos] = b * AA + tid;
        }
    }
}

// ---------------------------------------------------------------------------
// Kernel 3: fused fill + sparse MLP.
// Grid 512: block bx owns output-row window [64bx, 64bx+64).
//  - FILL: threads <128 compute the constant row gelu(b1)@W2 + b2 and write
//    it to the window's empty rows (cnt==0). Blocks past the compacted-row
//    count do only this (they exit early and free the SM).
//  - MLP: 512 threads, TMR=64 compacted rows, 16 warps x 4 rows each.
//    Pooling fused into x-staging via member-mask gather (no atomics).
//    Weights in SMEM transposed [c][k] with XOR swizzle (conflict-free
//    LDS.128); inner loop uses packed fma.rn.f32x2 (2 FMA/instr).
// SMEM: W1T 64KB + W2T 64KB + x/h 32KB + gb1/srid/scnt = 164,864 B dynamic.
// ---------------------------------------------------------------------------
__global__ __launch_bounds__(512, 1)
void mlp_fill_kernel(const float* __restrict__ emb,
                     const float* __restrict__ W1, const float* __restrict__ b1,
                     const float* __restrict__ W2, const float* __restrict__ b2,
                     float* __restrict__ out)
{
    extern __shared__ float sm[];
    float* sW1T = sm;                  // 16384 floats (4096 float4 slots)
    float* sW2T = sm + 16384;          // 16384
    float* sx   = sm + 32768;          // TMR*DD = 8192
    float* gb1s = sm + 40960;          // 128
    int*   srid = (int*)(sm + 41088);  // 64
    int*   scnt = (int*)(sm + 41152);  // 64

    const int n    = g_nrows;
    const int tid  = threadIdx.x;
    const int base = blockIdx.x * TMR;     // both fill window start & row base
    const bool do_mma = (base < n);

    if (tid < DD) gb1s[tid] = gelu_exact(b1[tid]);
    if (tid < TMR) {
        scnt[tid] = g_cnt[base + tid];
        int idx = base + tid;
        srid[tid] = do_mma ? g_rowlist[idx < n ? idx : n - 1] : 0;
    }

    // stage transposed + swizzled weights: slot(c,g) = c*32 + (g ^ ((c>>2)&7))
    if (do_mma) {
        float4* w1t = (float4*)sW1T;
        float4* w2t = (float4*)sW2T;
#pragma unroll
        for (int it = 0; it < 8; it++) {
            int i = tid + it * 512;
            int c = i & 127, g = i >> 7;
            int slot = c * 32 + (g ^ ((c >> 2) & 7));
            float4 v1, v2;
            v1.x = W1[(4 * g + 0) * DD + c];
            v1.y = W1[(4 * g + 1) * DD + c];
            v1.z = W1[(4 * g + 2) * DD + c];
            v1.w = W1[(4 * g + 3) * DD + c];
            v2.x = W2[(4 * g + 0) * DD + c];
            v2.y = W2[(4 * g + 1) * DD + c];
            v2.z = W2[(4 * g + 2) * DD + c];
            v2.w = W2[(4 * g + 3) * DD + c];
            w1t[slot] = v1;
            w2t[slot] = v2;
        }
    }
    __syncthreads();

    // FILL: constant row for empty groups in this block's window
    if (tid < DD) {
        float a0 = b2[tid], a1 = 0.f, a2 = 0.f, a3 = 0.f;
#pragma unroll 4
        for (int k = 0; k < DD; k += 4) {
            a0 = fmaf(gb1s[k + 0], W2[(k + 0) * DD + tid], a0);
            a1 = fmaf(gb1s[k + 1], W2[(k + 1) * DD + tid], a1);
            a2 = fmaf(gb1s[k + 2], W2[(k + 2) * DD + tid], a2);
            a3 = fmaf(gb1s[k + 3], W2[(k + 3) * DD + tid], a3);
        }
        float cf = (a0 + a1) + (a2 + a3);
        for (int r = 0; r < TMR; r++)
            if (scnt[r] == 0) out[(size_t)(base + r) * DD + tid] = cf;
    }
    if (!do_mma) return;

    const int wp   = tid >> 5;
    const int lane = tid & 31;
    const int r0   = wp * 4;        // 4 rows per warp (16 warps * 4 = 64)
    const int c0   = lane * 4;      // 4 cols per lane
    const int swl  = lane & 7;

    // stage x rows r0..r0+3: gather member rows of each group, mean in regs.
    // lane covers dims [4*lane, 4*lane+4).
#pragma unroll 1
    for (int r = r0; r < r0 + 4; r++) {
        const int gr = srid[r];
        const unsigned mw = g_members[(size_t)gr * 32 + lane];
        unsigned nz = __ballot_sync(0xffffffffu, mw != 0);
        const float* ebase = emb + (size_t)(gr & ~(AA - 1)) * DD;  // batch base
        float4 a4 = make_float4(0.f, 0.f, 0.f, 0.f);
        while (nz) {
            int w2i = __ffs(nz) - 1;
            nz &= nz - 1u;
            unsigned m = __shfl_sync(0xffffffffu, mw, w2i);
            while (m) {
                int bit = __ffs(m) - 1;
                m &= m - 1u;
                float4 v = *((const float4*)(ebase + (size_t)((w2i << 5) + bit) * DD) + lane);
                a4.x += v.x; a4.y += v.y; a4.z += v.z; a4.w += v.w;
            }
        }
        int c = __reduce_add_sync(0xffffffffu, (int)__popc(mw));
        float inv = 1.0f / (float)(c > 1 ? c : 1);
        a4.x *= inv; a4.y *= inv; a4.z *= inv; a4.w *= inv;
        *(float4*)&sx[r * DD + c0] = a4;
    }
    __syncwarp();   // warp owns its rows; x within-warp visible

    u64 acc[4][4];

    // ================= layer 1 =================
#pragma unroll
    for (int r = 0; r < 4; r++)
#pragma unroll
        for (int cc = 0; cc < 4; cc++) acc[r][cc] = 0ull;

    {
        const ulonglong2* wp4 = (const ulonglong2*)sW1T;
#pragma unroll 4
        for (int g = 0; g < 32; g++) {
            const int gs = g ^ swl;
            ulonglong2 wv0 = wp4[(c0 + 0) * 32 + gs];
            ulonglong2 wv1 = wp4[(c0 + 1) * 32 + gs];
            ulonglong2 wv2 = wp4[(c0 + 2) * 32 + gs];
            ulonglong2 wv3 = wp4[(c0 + 3) * 32 + gs];
#pragma unroll
            for (int r = 0; r < 4; r++) {
                ulonglong2 xv = *(const ulonglong2*)(sx + (r0 + r) * DD + 4 * g);
                asm("fma.rn.f32x2 %0, %1, %2, %0;" : "+l"(acc[r][0]) : "l"(xv.x), "l"(wv0.x));
                asm("fma.rn.f32x2 %0, %1, %2, %0;" : "+l"(acc[r][1]) : "l"(xv.x), "l"(wv1.x));
                asm("fma.rn.f32x2 %0, %1, %2, %0;" : "+l"(acc[r][2]) : "l"(xv.x), "l"(wv2.x));
                asm("fma.rn.f32x2 %0, %1, %2, %0;" : "+l"(acc[r][3]) : "l"(xv.x), "l"(wv3.x));
                asm("fma.rn.f32x2 %0, %1, %2, %0;" : "+l"(acc[r][0]) : "l"(xv.y), "l"(wv0.y));
                asm("fma.rn.f32x2 %0, %1, %2, %0;" : "+l"(acc[r][1]) : "l"(xv.y), "l"(wv1.y));
                asm("fma.rn.f32x2 %0, %1, %2, %0;" : "+l"(acc[r][2]) : "l"(xv.y), "l"(wv2.y));
                asm("fma.rn.f32x2 %0, %1, %2, %0;" : "+l"(acc[r][3]) : "l"(xv.y), "l"(wv3.y));
            }
        }
    }
    // epilogue 1: h = gelu(lo+hi + b1); warp owns its rows -> no barrier
    {
        float4 bv = *(const float4*)&b1[c0];
#pragma unroll
        for (int r = 0; r < 4; r++) {
            float4 h;
            h.x = gelu_exact(__uint_as_float((unsigned)acc[r][0]) + __uint_as_float((unsigned)(acc[r][0] >> 32)) + bv.x);
            h.y = gelu_exact(__uint_as_float((unsigned)acc[r][1]) + __uint_as_float((unsigned)(acc[r][1] >> 32)) + bv.y);
            h.z = gelu_exact(__uint_as_float((unsigned)acc[r][2]) + __uint_as_float((unsigned)(acc[r][2] >> 32)) + bv.z);
            h.w = gelu_exact(__uint_as_float((unsigned)acc[r][3]) + __uint_as_float((unsigned)(acc[r][3] >> 32)) + bv.w);
            *(float4*)&sx[(r0 + r) * DD + c0] = h;
        }
    }
    __syncwarp();

    // ================= layer 2 =================
#pragma unroll
    for (int r = 0; r < 4; r++)
#pragma unroll
        for (int cc = 0; cc < 4; cc++) acc[r][cc] = 0ull;

    {
        const ulonglong2* wp4 = (const ulonglong2*)sW2T;
#pragma unroll 4
        for (int g = 0; g < 32; g++) {
            const int gs = g ^ swl;
            ulonglong2 wv0 = wp4[(c0 + 0) * 32 + gs];
            ulonglong2 wv1 = wp4[(c0 + 1) * 32 + gs];
            ulonglong2 wv2 = wp4[(c0 + 2) * 32 + gs];
            ulonglong2 wv3 = wp4[(c0 + 3) * 32 + gs];
#pragma unroll
            for (int r = 0; r < 4; r++) {
                ulonglong2 xv = *(const ulonglong2*)(sx + (r0 + r) * DD + 4 * g);
                asm("fma.rn.f32x2 %0, %1, %2, %0;" : "+l"(acc[r][0]) : "l"(xv.x), "l"(wv0.x));
                asm("fma.rn.f32x2 %0, %1, %2, %0;" : "+l"(acc[r][1]) : "l"(xv.x), "l"(wv1.x));
                asm("fma.rn.f32x2 %0, %1, %2, %0;" : "+l"(acc[r][2]) : "l"(xv.x), "l"(wv2.x));
                asm("fma.rn.f32x2 %0, %1, %2, %0;" : "+l"(acc[r][3]) : "l"(xv.x), "l"(wv3.x));
                asm("fma.rn.f32x2 %0, %1, %2, %0;" : "+l"(acc[r][0]) : "l"(xv.y), "l"(wv0.y));
                asm("fma.rn.f32x2 %0, %1, %2, %0;" : "+l"(acc[r][1]) : "l"(xv.y), "l"(wv1.y));
                asm("fma.rn.f32x2 %0, %1, %2, %0;" : "+l"(acc[r][2]) : "l"(xv.y), "l"(wv2.y));
                asm("fma.rn.f32x2 %0, %1, %2, %0;" : "+l"(acc[r][3]) : "l"(xv.y), "l"(wv3.y));
            }
        }
    }
    // epilogue 2: out = lo+hi + b2, scatter to real rows
    {
        float4 bv = *(const float4*)&b2[c0];
#pragma unroll
        for (int r = 0; r < 4; r++) {
            int idx = base + r0 + r;
            if (idx < n) {
                int gr = srid[r0 + r];
                float4 ov;
                ov.x = __uint_as_float((unsigned)acc[r][0]) + __uint_as_float((unsigned)(acc[r][0] >> 32)) + bv.x;
                ov.y = __uint_as_float((unsigned)acc[r][1]) + __uint_as_float((unsigned)(acc[r][1] >> 32)) + bv.y;
                ov.z = __uint_as_float((unsigned)acc[r][2]) + __uint_as_float((unsigned)(acc[r][2] >> 32)) + bv.z;
                ov.w = __uint_as_float((unsigned)acc[r][3]) + __uint_as_float((unsigned)(acc[r][3] >> 32)) + bv.w;
                *(float4*)&out[(size_t)gr * DD + c0] = ov;
            }
        }
    }
}

// ---------------------------------------------------------------------------
extern "C" void kernel_launch(void* const* d_in, const int* in_sizes, int n_in,
                              void* d_out, int out_size)
{
    const float* emb    = (const float*)d_in[0];
    const float* coords = (const float*)d_in[1];
    const int*   mask   = (const int*)d_in[2];
    const float* W1     = (const float*)d_in[3];
    const float* b1     = (const float*)d_in[4];
    const float* W2     = (const float*)d_in[5];
    const float* b2     = (const float*)d_in[6];

    float* out = (float*)d_out;
    const int tok_elems = BB * AA * DD;
    float* out_mask = (out_size >= tok_elems + BB * AA)     ? out + tok_elems           : nullptr;
    float* out_a2g  = (out_size >= tok_elems + 2 * BB * AA) ? out + tok_elems + BB * AA : nullptr;

    const int smem_scan = AA * 32 * 4 + AA * 4 + AA * 4 + 32 * 4;              // 139,392
    const int smem_mlp  = (16384 + 16384 + TMR * DD + DD) * 4 + 2 * TMR * 4;   // 164,864

    cudaFuncSetAttribute(scan_kernel,
                         cudaFuncAttributeMaxDynamicSharedMemorySize, smem_scan);
    cudaFuncSetAttribute(mlp_fill_kernel,
                         cudaFuncAttributeMaxDynamicSharedMemorySize, smem_mlp);

    void* nrows_ptr = nullptr;
    cudaGetSymbolAddress(&nrows_ptr, g_nrows);

    cudaMemsetAsync(nrows_ptr, 0, sizeof(int));
    adj_kernel<<<dim3(8, BB), 1024>>>(coords);
    scan_kernel<<<BB, 1024, smem_scan>>>(mask, out_mask, out_a2g);
    mlp_fill_kernel<<<(BB * AA) / TMR, 512, smem_mlp>>>(emb, W1, b1, W2, b2, out);
}